// round 10
// baseline (speedup 1.0000x reference)
#include <cuda_runtime.h>
#include <cuda_fp16.h>
#include <cstdint>

// Problem constants
#define BB 4096
#define OO 11008
#define KK 4096
#define GG 32               // K / group_size (one group = 128 k = 128 bytes int8)

// GEMM tiling: CTA = 128M x 128N; N split 64 tensor + 64 dp4a
#define MT 128
#define NT 128
#define MTILES (BB / MT)    // 32
#define NTILES (OO / NT)    // 86
#define STAGES 4
#define STAGE_BYTES 32768   // (128 A rows + 128 B rows) * 128 k-bytes
#define SCALE_BYTES 32768   // a-scales 16KB + w-scales 16KB (f32)
#define SMEM_TOTAL (SCALE_BYTES + STAGES * STAGE_BYTES)   // 163840

// plain row-major int8 scratch
__device__ __align__(1024) uint8_t g_xq[(size_t)BB * KK];  // 16.8 MB
__device__ __align__(1024) uint8_t g_wq[(size_t)OO * KK];  // 45 MB

// ---------------------------------------------------------------- helpers
__device__ __forceinline__ uint32_t smem_u32(const void* p) {
    uint32_t a;
    asm("{ .reg .u64 t; cvta.to.shared.u64 t, %1; cvt.u32.u64 %0, t; }" : "=r"(a) : "l"(p));
    return a;
}
__device__ __forceinline__ void cp16(uint32_t s, const void* g) {
    asm volatile("cp.async.cg.shared.global [%0], [%1], 16;" :: "r"(s), "l"(g));
}
__device__ __forceinline__ void cp_commit() {
    asm volatile("cp.async.commit_group;" ::: "memory");
}
__device__ __forceinline__ void cp_wait2() {
    asm volatile("cp.async.wait_group 2;" ::: "memory");
}
__device__ __forceinline__ void mma_s8(int* c, const uint32_t* a, const uint32_t* b) {
    asm volatile(
        "mma.sync.aligned.m16n8k32.row.col.s32.s8.s8.s32 "
        "{%0,%1,%2,%3}, {%4,%5,%6,%7}, {%8,%9}, {%0,%1,%2,%3};"
        : "+r"(c[0]), "+r"(c[1]), "+r"(c[2]), "+r"(c[3])
        : "r"(a[0]), "r"(a[1]), "r"(a[2]), "r"(a[3]), "r"(b[0]), "r"(b[1]));
}

// ---------------------------------------------------------------- prepack (fused)
#define TOTX (BB * KK / 2)
#define TOTW (OO * KK / 2)
__global__ void __launch_bounds__(256) prepack_all(const int* __restrict__ px,
                                                   const int* __restrict__ pw) {
    int i = blockIdx.x * blockDim.x + threadIdx.x;
    const int* src;
    char2* dst;
    int j;
    if (i < TOTX) { src = px; dst = (char2*)g_xq; j = i; }
    else if (i < TOTX + TOTW) { src = pw; dst = (char2*)g_wq; j = i - TOTX; }
    else return;
    int v = src[j];
    int lo = ((v & 15) ^ 8) - 8;
    int hi = (((v >> 4) & 15) ^ 8) - 8;
    dst[j] = make_char2((char)lo, (char)hi);
}

// ---------------------------------------------------------------- GEMM (hybrid)
// smem per stage: A rows 0..127 then B rows 0..127, each row 128 bytes.
// row layout: eight 16B chunks, chunk c stored at phys = c ^ (row & 7).
__global__ void __launch_bounds__(256, 1)
gemm_kernel(const float* __restrict__ a_scale, const float* __restrict__ w_scale,
            const float* __restrict__ bias, float* __restrict__ out) {
    extern __shared__ uint8_t smem[];
    float* s_as = (float*)smem;                    // [32 groups][128 rows]
    float* s_ws = (float*)(smem + 16384);          // [32 groups][128 cols]
    uint8_t* s_data = smem + SCALE_BYTES;

    int tid = threadIdx.x, wid = tid >> 5, lane = tid & 31;
    int g8 = lane >> 2, tig = lane & 3;
    // tensor: 2x4 warp grid over 128M x 64N, warp tile 64x16
    int warp_m = (wid & 1) * 64;
    int warp_n = (wid >> 1) * 16;
    // dp4a: thread grid 32x8 over 128M x 64N (cols 64..127), thread tile 4M x 8N
    int dr0 = (tid >> 3) * 4;            // dp4a row base 0..124
    int dc0 = 64 + (tid & 7) * 8;        // dp4a col base 64..120

    // supertile rasterization (8 m-tiles per group) for L2 reuse
    int bid = blockIdx.x;
    int grp = bid / (8 * NTILES);
    int rem = bid - grp * (8 * NTILES);
    int mt = grp * 8 + (rem & 7);
    int nt = rem >> 3;
    int m0 = mt * MT, n0 = nt * NT;

    // stage scales once per CTA, transposed to [group][row]
    #pragma unroll 4
    for (int i = tid; i < 4096; i += 256) {
        int g = i >> 7, r = i & 127;
        s_as[i] = __ldg(a_scale + (size_t)(m0 + r) * GG + g);
        s_ws[i] = __ldg(w_scale + (size_t)(n0 + r) * GG + g);
    }

    const uint8_t* gA = g_xq + (size_t)m0 * KK;
    const uint8_t* gB = g_wq + (size_t)n0 * KK;

#define LOAD_STAGE(slot, g_)                                                       \
    do {                                                                           \
        uint32_t st_ = smem_u32(s_data + (slot) * STAGE_BYTES);                    \
        _Pragma("unroll")                                                          \
        for (int it_ = 0; it_ < 8; it_++) {                                        \
            int j_ = tid + 256 * it_;                                              \
            int r_ = (j_ >> 3) & 127;                                              \
            int c_ = j_ & 7;                                                       \
            int phys_ = c_ ^ (r_ & 7);                                             \
            uint32_t sa_ = st_ + (uint32_t)((j_ >> 10) * 16384 + r_ * 128 + phys_ * 16); \
            const uint8_t* gp_ = ((j_ >> 10) ? gB : gA) + (size_t)r_ * KK + (g_) * 128 + c_ * 16; \
            cp16(sa_, gp_);                                                        \
        }                                                                          \
        cp_commit();                                                               \
    } while (0)

    LOAD_STAGE(0, 0);
    LOAD_STAGE(1, 1);
    LOAD_STAGE(2, 2);

    float accf[4][2][4];     // tensor f32 running acc
    float dfac[4][8];        // dp4a f32 running acc
    #pragma unroll
    for (int a = 0; a < 4; a++) {
        #pragma unroll
        for (int b = 0; b < 2; b++)
            #pragma unroll
            for (int c = 0; c < 4; c++) accf[a][b][c] = 0.f;
        #pragma unroll
        for (int j = 0; j < 8; j++) dfac[a][j] = 0.f;
    }

    for (int g = 0; g < GG; g++) {
        cp_wait2();
        __syncthreads();
        if (g + 3 < GG) LOAD_STAGE((g + 3) & 3, g + 3);

        const uint8_t* stA = s_data + (g & 3) * STAGE_BYTES;
        const uint8_t* stB = stA + 16384;

        // ---------- tensor: issue 32 IMMAs (queue on tensor pipe) ----------
        int accs[4][2][4];
        #pragma unroll
        for (int a = 0; a < 4; a++)
            #pragma unroll
            for (int b = 0; b < 2; b++)
                #pragma unroll
                for (int c = 0; c < 4; c++) accs[a][b][c] = 0;

        #pragma unroll
        for (int ks = 0; ks < 4; ks++) {
            int off0 = (((2 * ks)     ^ g8) << 4) + tig * 4;   // k = ks*32 + tig*4
            int off1 = (((2 * ks + 1) ^ g8) << 4) + tig * 4;   // k = ks*32 + 16 + tig*4
            uint32_t af[4][4];
            #pragma unroll
            for (int m = 0; m < 4; m++) {
                const uint8_t* p0 = stA + (warp_m + m * 16 + g8) * 128;
                af[m][0] = *(const uint32_t*)(p0 + off0);
                af[m][1] = *(const uint32_t*)(p0 + 1024 + off0);   // +8 rows
                af[m][2] = *(const uint32_t*)(p0 + off1);
                af[m][3] = *(const uint32_t*)(p0 + 1024 + off1);
            }
            uint32_t bf[2][2];
            #pragma unroll
            for (int n = 0; n < 2; n++) {
                const uint8_t* pb = stB + (warp_n + n * 8 + g8) * 128;
                bf[n][0] = *(const uint32_t*)(pb + off0);
                bf[n][1] = *(const uint32_t*)(pb + off1);
            }
            #pragma unroll
            for (int m = 0; m < 4; m++)
                #pragma unroll
                for (int n = 0; n < 2; n++)
                    mma_s8(accs[m][n], af[m], bf[n]);
        }

        // ---------- dp4a: 1024 dp4a on the fma pipe while IMMAs drain ----------
        int dacc[4][8];
        #pragma unroll
        for (int i = 0; i < 4; i++)
            #pragma unroll
            for (int j = 0; j < 8; j++) dacc[i][j] = 0;

        #pragma unroll
        for (int k16 = 0; k16 < 8; k16++) {
            uint4 a4[4];
            #pragma unroll
            for (int i = 0; i < 4; i++) {
                int r = dr0 + i;
                a4[i] = *(const uint4*)(stA + r * 128 + ((k16 ^ (r & 7)) << 4));
            }
            uint4 b4[8];
            #pragma unroll
            for (int j = 0; j < 8; j++) {
                int c = dc0 + j;
                b4[j] = *(const uint4*)(stB + c * 128 + ((k16 ^ (c & 7)) << 4));
            }
            #pragma unroll
            for (int i = 0; i < 4; i++)
                #pragma unroll
                for (int j = 0; j < 8; j++) {
                    dacc[i][j] = __dp4a((int)a4[i].x, (int)b4[j].x, dacc[i][j]);
                    dacc[i][j] = __dp4a((int)a4[i].y, (int)b4[j].y, dacc[i][j]);
                    dacc[i][j] = __dp4a((int)a4[i].z, (int)b4[j].z, dacc[i][j]);
                    dacc[i][j] = __dp4a((int)a4[i].w, (int)b4[j].w, dacc[i][j]);
                }
        }

        // ---------- dequant: tensor side ----------
        {
            float rs[8], cs[4];
            #pragma unroll
            for (int m = 0; m < 4; m++) {
                int r = warp_m + m * 16 + g8;
                rs[2 * m]     = s_as[g * 128 + r];
                rs[2 * m + 1] = s_as[g * 128 + r + 8];
            }
            #pragma unroll
            for (int n = 0; n < 2; n++) {
                int c = warp_n + n * 8 + tig * 2;
                cs[2 * n]     = s_ws[g * 128 + c];
                cs[2 * n + 1] = s_ws[g * 128 + c + 1];
            }
            #pragma unroll
            for (int m = 0; m < 4; m++)
                #pragma unroll
                for (int n = 0; n < 2; n++) {
                    accf[m][n][0] += (float)accs[m][n][0] * (rs[2 * m]     * cs[2 * n]);
                    accf[m][n][1] += (float)accs[m][n][1] * (rs[2 * m]     * cs[2 * n + 1]);
                    accf[m][n][2] += (float)accs[m][n][2] * (rs[2 * m + 1] * cs[2 * n]);
                    accf[m][n][3] += (float)accs[m][n][3] * (rs[2 * m + 1] * cs[2 * n + 1]);
                }
        }

        // ---------- dequant: dp4a side ----------
        {
            float ra[4], cb[8];
            #pragma unroll
            for (int i = 0; i < 4; i++) ra[i] = s_as[g * 128 + dr0 + i];
            #pragma unroll
            for (int j = 0; j < 8; j++) cb[j] = s_ws[g * 128 + dc0 + j];
            #pragma unroll
            for (int i = 0; i < 4; i++)
                #pragma unroll
                for (int j = 0; j < 8; j++)
                    dfac[i][j] += (float)dacc[i][j] * (ra[i] * cb[j]);
        }
    }

    // ---------------- epilogue: tensor half (cols n0..n0+63) ----------------
    #pragma unroll
    for (int m = 0; m < 4; m++)
        #pragma unroll
        for (int n = 0; n < 2; n++) {
            int row = m0 + warp_m + m * 16 + g8;
            int col = n0 + warp_n + n * 8 + tig * 2;
            __half hb0 = __float2half_rn(__ldg(bias + col));
            __half hb1 = __float2half_rn(__ldg(bias + col + 1));
            float2 lo, hi;
            lo.x = __half2float(__hadd(__float2half_rn(accf[m][n][0]), hb0));
            lo.y = __half2float(__hadd(__float2half_rn(accf[m][n][1]), hb1));
            hi.x = __half2float(__hadd(__float2half_rn(accf[m][n][2]), hb0));
            hi.y = __half2float(__hadd(__float2half_rn(accf[m][n][3]), hb1));
            *(float2*)(out + (size_t)row * OO + col) = lo;
            *(float2*)(out + (size_t)(row + 8) * OO + col) = hi;
        }

    // ---------------- epilogue: dp4a half (cols n0+64..n0+127) ----------------
    #pragma unroll
    for (int i = 0; i < 4; i++) {
        int row = m0 + dr0 + i;
        int col = n0 + dc0;
        float vv[8];
        #pragma unroll
        for (int j = 0; j < 8; j++) {
            __half hb = __float2half_rn(__ldg(bias + col + j));
            vv[j] = __half2float(__hadd(__float2half_rn(dfac[i][j]), hb));
        }
        *(float4*)(out + (size_t)row * OO + col)     = make_float4(vv[0], vv[1], vv[2], vv[3]);
        *(float4*)(out + (size_t)row * OO + col + 4) = make_float4(vv[4], vv[5], vv[6], vv[7]);
    }
}

// ---------------------------------------------------------------- host
extern "C" void kernel_launch(void* const* d_in, const int* in_sizes, int n_in,
                              void* d_out, int out_size) {
    const int*   x        = (const int*)d_in[0];
    const float* a_scale  = (const float*)d_in[1];   // fp16 in reference -> float32 in harness
    const int*   w_packed = (const int*)d_in[2];
    const float* w_scale  = (const float*)d_in[3];
    const float* bias     = (const float*)d_in[4];
    float*       out      = (float*)d_out;

    int tot = TOTX + TOTW;
    prepack_all<<<(tot + 255) / 256, 256>>>(x, w_packed);

    static bool attr_set = false;
    if (!attr_set) {
        cudaFuncSetAttribute(gemm_kernel, cudaFuncAttributeMaxDynamicSharedMemorySize, SMEM_TOTAL);
        attr_set = true;
    }
    gemm_kernel<<<MTILES * NTILES, 256, SMEM_TOTAL>>>(a_scale, w_scale, bias, out);
}

// round 11
// speedup vs baseline: 2.9253x; 2.9253x over previous
#include <cuda_runtime.h>
#include <cuda_fp16.h>
#include <cstdint>

// Problem constants
#define BB 4096
#define OO 11008
#define KK 4096
#define GG 32               // K / group_size (one group = 128 k = 128 bytes int8)

// GEMM tiling: CTA = 128M x 128N; cols 0..63 tensor warps, 64..127 dp4a warps
#define MT 128
#define NT 128
#define MTILES (BB / MT)    // 32
#define NTILES (OO / NT)    // 86
#define STAGES 4
#define STAGE_BYTES 32768   // (128 A rows + 128 B rows) * 128 k-bytes
#define SCALE_BYTES 32768   // a-scales 16KB + w-scales 16KB (f32)
#define SMEM_TOTAL (SCALE_BYTES + STAGES * STAGE_BYTES)   // 163840
#define NTHREADS 512

// plain row-major int8 scratch
__device__ __align__(1024) uint8_t g_xq[(size_t)BB * KK];  // 16.8 MB
__device__ __align__(1024) uint8_t g_wq[(size_t)OO * KK];  // 45 MB

// ---------------------------------------------------------------- helpers
__device__ __forceinline__ uint32_t smem_u32(const void* p) {
    uint32_t a;
    asm("{ .reg .u64 t; cvta.to.shared.u64 t, %1; cvt.u32.u64 %0, t; }" : "=r"(a) : "l"(p));
    return a;
}
__device__ __forceinline__ void cp16(uint32_t s, const void* g) {
    asm volatile("cp.async.cg.shared.global [%0], [%1], 16;" :: "r"(s), "l"(g));
}
__device__ __forceinline__ void cp_commit() {
    asm volatile("cp.async.commit_group;" ::: "memory");
}
__device__ __forceinline__ void cp_wait2() {
    asm volatile("cp.async.wait_group 2;" ::: "memory");
}
__device__ __forceinline__ void mma_s8(int* c, const uint32_t* a, const uint32_t* b) {
    asm volatile(
        "mma.sync.aligned.m16n8k32.row.col.s32.s8.s8.s32 "
        "{%0,%1,%2,%3}, {%4,%5,%6,%7}, {%8,%9}, {%0,%1,%2,%3};"
        : "+r"(c[0]), "+r"(c[1]), "+r"(c[2]), "+r"(c[3])
        : "r"(a[0]), "r"(a[1]), "r"(a[2]), "r"(a[3]), "r"(b[0]), "r"(b[1]));
}

// ---------------------------------------------------------------- prepack (fused)
#define TOTX (BB * KK / 2)
#define TOTW (OO * KK / 2)
__global__ void __launch_bounds__(256) prepack_all(const int* __restrict__ px,
                                                   const int* __restrict__ pw) {
    int i = blockIdx.x * blockDim.x + threadIdx.x;
    const int* src;
    char2* dst;
    int j;
    if (i < TOTX) { src = px; dst = (char2*)g_xq; j = i; }
    else if (i < TOTX + TOTW) { src = pw; dst = (char2*)g_wq; j = i - TOTX; }
    else return;
    int v = src[j];
    int lo = ((v & 15) ^ 8) - 8;
    int hi = (((v >> 4) & 15) ^ 8) - 8;
    dst[j] = make_char2((char)lo, (char)hi);
}

// ---------------------------------------------------------------- GEMM (warp-specialized hybrid)
// smem per stage: A rows 0..127 then B rows 0..127, each row 128 bytes.
// row layout: eight 16B chunks, chunk c stored at phys = c ^ (row & 7).
__global__ void __launch_bounds__(NTHREADS, 1)
gemm_kernel(const float* __restrict__ a_scale, const float* __restrict__ w_scale,
            const float* __restrict__ bias, float* __restrict__ out) {
    extern __shared__ uint8_t smem[];
    float* s_as = (float*)smem;                    // [32 groups][128 rows]
    float* s_ws = (float*)(smem + 16384);          // [32 groups][128 cols]
    uint8_t* s_data = smem + SCALE_BYTES;

    int tid = threadIdx.x, wid = tid >> 5, lane = tid & 31;
    int g8 = lane >> 2, tig = lane & 3;

    // supertile rasterization (8 m-tiles per group) for L2 reuse
    int bid = blockIdx.x;
    int grp = bid / (8 * NTILES);
    int rem = bid - grp * (8 * NTILES);
    int mt = grp * 8 + (rem & 7);
    int nt = rem >> 3;
    int m0 = mt * MT, n0 = nt * NT;

    // stage scales once per CTA, transposed to [group][row]
    #pragma unroll 2
    for (int i = tid; i < 4096; i += NTHREADS) {
        int g = i >> 7, r = i & 127;
        s_as[i] = __ldg(a_scale + (size_t)(m0 + r) * GG + g);
        s_ws[i] = __ldg(w_scale + (size_t)(n0 + r) * GG + g);
    }

    const uint8_t* gA = g_xq + (size_t)m0 * KK;
    const uint8_t* gB = g_wq + (size_t)n0 * KK;

    // loader: 2048 x 16B per stage, 4 cp16 per thread
#define LOAD_STAGE(slot, g_)                                                       \
    do {                                                                           \
        uint32_t st_ = smem_u32(s_data + (slot) * STAGE_BYTES);                    \
        _Pragma("unroll")                                                          \
        for (int it_ = 0; it_ < 4; it_++) {                                        \
            int j_ = tid + NTHREADS * it_;                                         \
            int r_ = (j_ >> 3) & 127;                                              \
            int c_ = j_ & 7;                                                       \
            int phys_ = c_ ^ (r_ & 7);                                             \
            uint32_t sa_ = st_ + (uint32_t)((j_ >> 10) * 16384 + r_ * 128 + phys_ * 16); \
            const uint8_t* gp_ = ((j_ >> 10) ? gB : gA) + (size_t)r_ * KK + (g_) * 128 + c_ * 16; \
            cp16(sa_, gp_);                                                        \
        }                                                                          \
        cp_commit();                                                               \
    } while (0)

    LOAD_STAGE(0, 0);
    LOAD_STAGE(1, 1);
    LOAD_STAGE(2, 2);

    if (wid < 8) {
        // ================= TENSOR warps: cols 0..63 =================
        // warp grid 4M x 2N, warp tile 32M x 32N
        int warp_m = (wid & 3) * 32;
        int warp_n = (wid >> 2) * 32;

        float accf[2][4][4];
        #pragma unroll
        for (int a = 0; a < 2; a++)
            #pragma unroll
            for (int b = 0; b < 4; b++)
                #pragma unroll
                for (int c = 0; c < 4; c++) accf[a][b][c] = 0.f;

        for (int g = 0; g < GG; g++) {
            cp_wait2();
            __syncthreads();
            if (g + 3 < GG) LOAD_STAGE((g + 3) & 3, g + 3);

            const uint8_t* stA = s_data + (g & 3) * STAGE_BYTES;
            const uint8_t* stB = stA + 16384;

            int accs[2][4][4];
            #pragma unroll
            for (int a = 0; a < 2; a++)
                #pragma unroll
                for (int b = 0; b < 4; b++)
                    #pragma unroll
                    for (int c = 0; c < 4; c++) accs[a][b][c] = 0;

            #pragma unroll
            for (int ks = 0; ks < 4; ks++) {
                int off0 = (((2 * ks)     ^ g8) << 4) + tig * 4;   // k = ks*32 + tig*4
                int off1 = (((2 * ks + 1) ^ g8) << 4) + tig * 4;   // + 16
                uint32_t af[2][4];
                #pragma unroll
                for (int m = 0; m < 2; m++) {
                    const uint8_t* p0 = stA + (warp_m + m * 16 + g8) * 128;
                    af[m][0] = *(const uint32_t*)(p0 + off0);
                    af[m][1] = *(const uint32_t*)(p0 + 1024 + off0);   // +8 rows
                    af[m][2] = *(const uint32_t*)(p0 + off1);
                    af[m][3] = *(const uint32_t*)(p0 + 1024 + off1);
                }
                uint32_t bf[4][2];
                #pragma unroll
                for (int n = 0; n < 4; n++) {
                    const uint8_t* pb = stB + (warp_n + n * 8 + g8) * 128;
                    bf[n][0] = *(const uint32_t*)(pb + off0);
                    bf[n][1] = *(const uint32_t*)(pb + off1);
                }
                #pragma unroll
                for (int m = 0; m < 2; m++)
                    #pragma unroll
                    for (int n = 0; n < 4; n++)
                        mma_s8(accs[m][n], af[m], bf[n]);
            }

            float rs[4], cs[8];
            #pragma unroll
            for (int m = 0; m < 2; m++) {
                int r = warp_m + m * 16 + g8;
                rs[2 * m]     = s_as[g * 128 + r];
                rs[2 * m + 1] = s_as[g * 128 + r + 8];
            }
            #pragma unroll
            for (int n = 0; n < 4; n++) {
                int c = warp_n + n * 8 + tig * 2;
                cs[2 * n]     = s_ws[g * 128 + c];
                cs[2 * n + 1] = s_ws[g * 128 + c + 1];
            }
            #pragma unroll
            for (int m = 0; m < 2; m++)
                #pragma unroll
                for (int n = 0; n < 4; n++) {
                    accf[m][n][0] += (float)accs[m][n][0] * (rs[2 * m]     * cs[2 * n]);
                    accf[m][n][1] += (float)accs[m][n][1] * (rs[2 * m]     * cs[2 * n + 1]);
                    accf[m][n][2] += (float)accs[m][n][2] * (rs[2 * m + 1] * cs[2 * n]);
                    accf[m][n][3] += (float)accs[m][n][3] * (rs[2 * m + 1] * cs[2 * n + 1]);
                }
        }

        // epilogue (cols n0..n0+63)
        #pragma unroll
        for (int m = 0; m < 2; m++)
            #pragma unroll
            for (int n = 0; n < 4; n++) {
                int row = m0 + warp_m + m * 16 + g8;
                int col = n0 + warp_n + n * 8 + tig * 2;
                __half hb0 = __float2half_rn(__ldg(bias + col));
                __half hb1 = __float2half_rn(__ldg(bias + col + 1));
                float2 lo, hi;
                lo.x = __half2float(__hadd(__float2half_rn(accf[m][n][0]), hb0));
                lo.y = __half2float(__hadd(__float2half_rn(accf[m][n][1]), hb1));
                hi.x = __half2float(__hadd(__float2half_rn(accf[m][n][2]), hb0));
                hi.y = __half2float(__hadd(__float2half_rn(accf[m][n][3]), hb1));
                *(float2*)(out + (size_t)row * OO + col) = lo;
                *(float2*)(out + (size_t)(row + 8) * OO + col) = hi;
            }
    } else {
        // ================= DP4A warps: cols 64..127 =================
        int dtid = tid - 256;                 // 0..255
        int dr0 = (dtid >> 3) * 4;            // row base 0..124
        int dc0 = 64 + (dtid & 7) * 8;        // col base 64..120
        int rot = 2 * (lane & 7);             // k8 rotation: lanes sharing a bank-set
                                              // read distinct chunks each step

        float dfac[4][8];
        #pragma unroll
        for (int i = 0; i < 4; i++)
            #pragma unroll
            for (int j = 0; j < 8; j++) dfac[i][j] = 0.f;

        for (int g = 0; g < GG; g++) {
            cp_wait2();
            __syncthreads();
            if (g + 3 < GG) LOAD_STAGE((g + 3) & 3, g + 3);

            const uint8_t* stA = s_data + (g & 3) * STAGE_BYTES;
            const uint8_t* stB = stA + 16384;

            int dacc[4][8];
            #pragma unroll
            for (int i = 0; i < 4; i++)
                #pragma unroll
                for (int j = 0; j < 8; j++) dacc[i][j] = 0;

            #pragma unroll
            for (int st = 0; st < 16; st++) {
                int s = (st + rot) & 15;       // k8 index (8 k-values = 8 bytes)
                int ch = s >> 1, sub = (s & 1) * 8;
                uint2 a2[4];
                #pragma unroll
                for (int i = 0; i < 4; i++) {
                    int r = dr0 + i;
                    a2[i] = *(const uint2*)(stA + r * 128 + ((ch ^ (r & 7)) << 4) + sub);
                }
                uint2 b2[8];
                #pragma unroll
                for (int j = 0; j < 8; j++) {
                    int c = dc0 + j;
                    b2[j] = *(const uint2*)(stB + c * 128 + ((ch ^ (c & 7)) << 4) + sub);
                }
                #pragma unroll
                for (int i = 0; i < 4; i++)
                    #pragma unroll
                    for (int j = 0; j < 8; j++) {
                        dacc[i][j] = __dp4a((int)a2[i].x, (int)b2[j].x, dacc[i][j]);
                        dacc[i][j] = __dp4a((int)a2[i].y, (int)b2[j].y, dacc[i][j]);
                    }
            }

            float ra[4], cb[8];
            #pragma unroll
            for (int i = 0; i < 4; i++) ra[i] = s_as[g * 128 + dr0 + i];
            #pragma unroll
            for (int j = 0; j < 8; j++) cb[j] = s_ws[g * 128 + dc0 + j];
            #pragma unroll
            for (int i = 0; i < 4; i++)
                #pragma unroll
                for (int j = 0; j < 8; j++)
                    dfac[i][j] += (float)dacc[i][j] * (ra[i] * cb[j]);
        }

        // epilogue (cols n0+64..n0+127)
        #pragma unroll
        for (int i = 0; i < 4; i++) {
            int row = m0 + dr0 + i;
            int col = n0 + dc0;
            float vv[8];
            #pragma unroll
            for (int j = 0; j < 8; j++) {
                __half hb = __float2half_rn(__ldg(bias + col + j));
                vv[j] = __half2float(__hadd(__float2half_rn(dfac[i][j]), hb));
            }
            *(float4*)(out + (size_t)row * OO + col)     = make_float4(vv[0], vv[1], vv[2], vv[3]);
            *(float4*)(out + (size_t)row * OO + col + 4) = make_float4(vv[4], vv[5], vv[6], vv[7]);
        }
    }
}

// ---------------------------------------------------------------- host
extern "C" void kernel_launch(void* const* d_in, const int* in_sizes, int n_in,
                              void* d_out, int out_size) {
    const int*   x        = (const int*)d_in[0];
    const float* a_scale  = (const float*)d_in[1];   // fp16 in reference -> float32 in harness
    const int*   w_packed = (const int*)d_in[2];
    const float* w_scale  = (const float*)d_in[3];
    const float* bias     = (const float*)d_in[4];
    float*       out      = (float*)d_out;

    int tot = TOTX + TOTW;
    prepack_all<<<(tot + 255) / 256, 256>>>(x, w_packed);

    static bool attr_set = false;
    if (!attr_set) {
        cudaFuncSetAttribute(gemm_kernel, cudaFuncAttributeMaxDynamicSharedMemorySize, SMEM_TOTAL);
        attr_set = true;
    }
    gemm_kernel<<<MTILES * NTILES, NTHREADS, SMEM_TOTAL>>>(a_scale, w_scale, bias, out);
}